// round 2
// baseline (speedup 1.0000x reference)
#include <cuda_runtime.h>
#include <cstdint>

#define BATCH 4
#define NPTS  8192
#define KNN   16
#define CIN   64
#define CO    64
#define F3    192   // 3*CO

// Scratch (static device globals — no allocation allowed)
__device__ int   g_idx[BATCH * NPTS * KNN];
__device__ float g_feat3[(size_t)BATCH * NPTS * F3];   // (B, N, 192) n-major

// ---------------------------------------------------------------------------
// Kernel 1: brute-force KNN, top-16 per query via register insertion sort.
// d2 = sq[n] + sq[m] - 2*dot  (same formula as reference)
// ---------------------------------------------------------------------------
#define KCHUNK 2048
__global__ void __launch_bounds__(128) knn_kernel(const float* __restrict__ coords) {
    __shared__ float4 s_pt[KCHUNK];   // x, y, z, |p|^2
    const int b = blockIdx.y;
    const int q = blockIdx.x * 128 + threadIdx.x;
    const float* cb = coords + (size_t)b * 3 * NPTS;

    const float qx = cb[q], qy = cb[NPTS + q], qz = cb[2 * NPTS + q];
    const float sqn = fmaf(qz, qz, fmaf(qy, qy, qx * qx));
    const float nx = -2.f * qx, ny = -2.f * qy, nz = -2.f * qz;

    float bd[KNN];
    int   bi[KNN];
#pragma unroll
    for (int j = 0; j < KNN; ++j) { bd[j] = 3.4e38f; bi[j] = 0; }

    for (int c0 = 0; c0 < NPTS; c0 += KCHUNK) {
        __syncthreads();
        for (int j = threadIdx.x; j < KCHUNK; j += 128) {
            float x = cb[c0 + j];
            float y = cb[NPTS + c0 + j];
            float z = cb[2 * NPTS + c0 + j];
            s_pt[j] = make_float4(x, y, z, fmaf(z, z, fmaf(y, y, x * x)));
        }
        __syncthreads();
#pragma unroll 4
        for (int j = 0; j < KCHUNK; ++j) {
            float4 p = s_pt[j];
            float d = fmaf(nx, p.x, fmaf(ny, p.y, fmaf(nz, p.z, sqn + p.w)));
            if (d < bd[KNN - 1]) {
                int mi = c0 + j;
#pragma unroll
                for (int t = 0; t < KNN; ++t) {
                    if (d < bd[t]) {
                        float td = bd[t]; int ti = bi[t];
                        bd[t] = d;  bi[t] = mi;
                        d = td;     mi = ti;
                    }
                }
            }
        }
    }
    int* op = g_idx + ((size_t)b * NPTS + q) * KNN;
#pragma unroll
    for (int j = 0; j < KNN; ++j) op[j] = bi[j];
}

// ---------------------------------------------------------------------------
// Kernel 2: feat3[b,n,o] = sum_c w_lin[o,c] * features[b,c,n]   (transposed out)
// ---------------------------------------------------------------------------
__global__ void __launch_bounds__(128) feat3_kernel(const float* __restrict__ features,
                                                    const float* __restrict__ w_lin) {
    __shared__ float sw[F3 * CIN];   // 48 KB
    for (int i = threadIdx.x; i < F3 * CIN; i += 128) sw[i] = w_lin[i];

    const int b = blockIdx.y;
    const int n = blockIdx.x * 128 + threadIdx.x;

    float f[CIN];
    const float* fb = features + (size_t)b * CIN * NPTS + n;
#pragma unroll
    for (int c = 0; c < CIN; ++c) f[c] = fb[(size_t)c * NPTS];
    __syncthreads();

    float* outp = g_feat3 + ((size_t)b * NPTS + n) * F3;
    const float4* sw4 = (const float4*)sw;
#pragma unroll 1
    for (int og = 0; og < F3 / 4; ++og) {
        float a0 = 0.f, a1 = 0.f, a2 = 0.f, a3 = 0.f;
#pragma unroll
        for (int c4 = 0; c4 < CIN / 4; ++c4) {
            float4 w0 = sw4[(og * 4 + 0) * 16 + c4];
            float4 w1 = sw4[(og * 4 + 1) * 16 + c4];
            float4 w2 = sw4[(og * 4 + 2) * 16 + c4];
            float4 w3 = sw4[(og * 4 + 3) * 16 + c4];
            int c = c4 * 4;
            a0 = fmaf(w0.x, f[c], fmaf(w0.y, f[c+1], fmaf(w0.z, f[c+2], fmaf(w0.w, f[c+3], a0))));
            a1 = fmaf(w1.x, f[c], fmaf(w1.y, f[c+1], fmaf(w1.z, f[c+2], fmaf(w1.w, f[c+3], a1))));
            a2 = fmaf(w2.x, f[c], fmaf(w2.y, f[c+1], fmaf(w2.z, f[c+2], fmaf(w2.w, f[c+3], a2))));
            a3 = fmaf(w3.x, f[c], fmaf(w3.y, f[c+1], fmaf(w3.z, f[c+2], fmaf(w3.w, f[c+3], a3))));
        }
        ((float4*)outp)[og] = make_float4(a0, a1, a2, a3);
    }
}

// ---------------------------------------------------------------------------
// Kernel 3: fused pos-encoding + gamma MLP + softmax + weighted sum.
// 256 threads = 4 point-groups x 64 channels. Weights transposed in shared.
// ---------------------------------------------------------------------------
#define PTS 4
__global__ void __launch_bounds__(256) fused_kernel(
    const float* __restrict__ coords,
    const float* __restrict__ w_theta1,
    const float* __restrict__ w_theta2,
    const float* __restrict__ w_gamma1,
    const float* __restrict__ w_gamma2,
    float* __restrict__ out) {
    extern __shared__ float smem[];
    float*  wt2T = smem;                 // [c][o]  64x64
    float*  wg1T = smem + 4096;
    float*  wg2T = smem + 8192;
    float*  wt1T = smem + 12288;         // [c][o]  3x64
    float*  svA  = smem + 12480;         // [grp][64]
    float*  svB  = smem + 12736;
    float4* srel = (float4*)(smem + 12992);  // [grp][16]
    int*    sidx = (int*)(smem + 13248);     // [grp][16]
    float*  s_ag = smem + 13312;         // [grp][k][o]
    float*  s_g  = smem + 17408;         // [grp][k][o]   total 21504 floats

    const int tid = threadIdx.x;
    for (int i = tid; i < 4096; i += 256) {
        int o = i >> 6, c = i & 63;
        wt2T[c * 64 + o] = w_theta2[i];
        wg1T[c * 64 + o] = w_gamma1[i];
        wg2T[c * 64 + o] = w_gamma2[i];
    }
    if (tid < 192) {
        int o = tid / 3, c = tid % 3;
        wt1T[c * 64 + o] = w_theta1[tid];
    }

    const int gq = tid >> 6;
    const int o  = tid & 63;
    const int P  = blockIdx.x * PTS + gq;
    const int b  = P >> 13;
    const int n  = P & (NPTS - 1);
    const int bbase = b * NPTS;

    if (o < KNN) {
        int k  = o;
        int ik = g_idx[(size_t)P * KNN + k];
        sidx[gq * KNN + k] = ik;
        const float* cb = coords + (size_t)b * 3 * NPTS;
        float rx = cb[n]            - cb[ik];
        float ry = cb[NPTS + n]     - cb[NPTS + ik];
        float rz = cb[2 * NPTS + n] - cb[2 * NPTS + ik];
        srel[gq * KNN + k] = make_float4(rx, ry, rz, 0.f);
    }
    const float phi = g_feat3[(size_t)P * F3 + o];
    __syncthreads();

#pragma unroll 1
    for (int k = 0; k < KNN; ++k) {
        float* b0 = (k & 1) ? svB : svA;
        float* b1 = (k & 1) ? svA : svB;

        float4 r = srel[gq * KNN + k];
        int ik   = sidx[gq * KNN + k];

        // t1 = w_theta1 @ rel
        float t1v = fmaf(wt1T[128 + o], r.z, fmaf(wt1T[64 + o], r.y, wt1T[o] * r.x));
        b0[gq * 64 + o] = t1v;
        __syncthreads();

        // delta = relu(w_theta2 @ t1)
        float acc = 0.f;
        {
            const float4* v4 = (const float4*)(b0 + gq * 64);
#pragma unroll
            for (int c4 = 0; c4 < 16; ++c4) {
                float4 v = v4[c4]; int c = c4 * 4;
                acc = fmaf(wt2T[(c    ) * 64 + o], v.x, acc);
                acc = fmaf(wt2T[(c + 1) * 64 + o], v.y, acc);
                acc = fmaf(wt2T[(c + 2) * 64 + o], v.z, acc);
                acc = fmaf(wt2T[(c + 3) * 64 + o], v.w, acc);
            }
        }
        float dlt = fmaxf(acc, 0.f);

        const float* fb = g_feat3 + (size_t)(bbase + ik) * F3;
        float psi   = fb[64 + o];
        float alpha = fb[128 + o];
        s_ag[(gq * KNN + k) * 64 + o] = alpha + dlt;
        float ig = (phi - psi) + dlt;
        b1[gq * 64 + o] = ig;
        __syncthreads();

        // g1 = w_gamma1 @ ig
        acc = 0.f;
        {
            const float4* v4 = (const float4*)(b1 + gq * 64);
#pragma unroll
            for (int c4 = 0; c4 < 16; ++c4) {
                float4 v = v4[c4]; int c = c4 * 4;
                acc = fmaf(wg1T[(c    ) * 64 + o], v.x, acc);
                acc = fmaf(wg1T[(c + 1) * 64 + o], v.y, acc);
                acc = fmaf(wg1T[(c + 2) * 64 + o], v.z, acc);
                acc = fmaf(wg1T[(c + 3) * 64 + o], v.w, acc);
            }
        }
        b0[gq * 64 + o] = acc;
        __syncthreads();

        // g = relu(w_gamma2 @ g1)
        acc = 0.f;
        {
            const float4* v4 = (const float4*)(b0 + gq * 64);
#pragma unroll
            for (int c4 = 0; c4 < 16; ++c4) {
                float4 v = v4[c4]; int c = c4 * 4;
                acc = fmaf(wg2T[(c    ) * 64 + o], v.x, acc);
                acc = fmaf(wg2T[(c + 1) * 64 + o], v.y, acc);
                acc = fmaf(wg2T[(c + 2) * 64 + o], v.z, acc);
                acc = fmaf(wg2T[(c + 3) * 64 + o], v.w, acc);
            }
        }
        s_g[(gq * KNN + k) * 64 + o] = fmaxf(acc, 0.f);
    }

    // softmax over k + weighted sum (reads only this thread's own writes)
    float m = -3.4e38f;
#pragma unroll
    for (int k = 0; k < KNN; ++k) m = fmaxf(m, s_g[(gq * KNN + k) * 64 + o]);
    float s = 0.f, num = 0.f;
#pragma unroll
    for (int k = 0; k < KNN; ++k) {
        float e = __expf(s_g[(gq * KNN + k) * 64 + o] - m);
        s += e;
        num = fmaf(e, s_ag[(gq * KNN + k) * 64 + o], num);
    }
    out[(size_t)(b * CO + o) * NPTS + n] = num / s;
}

// ---------------------------------------------------------------------------
extern "C" void kernel_launch(void* const* d_in, const int* in_sizes, int n_in,
                              void* d_out, int out_size) {
    const float* features = (const float*)d_in[0];
    const float* coords   = (const float*)d_in[1];
    const float* w_lin    = (const float*)d_in[2];
    const float* w_theta1 = (const float*)d_in[3];
    const float* w_theta2 = (const float*)d_in[4];
    const float* w_gamma1 = (const float*)d_in[5];
    const float* w_gamma2 = (const float*)d_in[6];
    float* out = (float*)d_out;

    static bool attr_set = false;
    if (!attr_set) {
        cudaFuncSetAttribute(fused_kernel, cudaFuncAttributeMaxDynamicSharedMemorySize,
                             21504 * sizeof(float));
        attr_set = true;
    }

    knn_kernel<<<dim3(NPTS / 128, BATCH), 128>>>(coords);
    feat3_kernel<<<dim3(NPTS / 128, BATCH), 128>>>(features, w_lin);
    fused_kernel<<<(BATCH * NPTS) / PTS, 256, 21504 * sizeof(float)>>>(
        coords, w_theta1, w_theta2, w_gamma1, w_gamma2, out);
}

// round 3
// speedup vs baseline: 1.9068x; 1.9068x over previous
#include <cuda_runtime.h>
#include <cstdint>

#define BATCH 4
#define NPTS  8192
#define KNN   16
#define CIN   64
#define CO    64
#define F3    192
#define CS    20      // staging row stride in floats (16B aligned: 80B)
#define PPT   4       // point-teams per block (64 threads each)

typedef unsigned long long ull;
typedef unsigned int uint;

__device__ int   g_idx[BATCH * NPTS * KNN];
__device__ float g_feat3[(size_t)BATCH * NPTS * F3];   // (B, N, 192)

// ---------------------------------------------------------------------------
// sorted top-16 insert (branchless select chain)
// ---------------------------------------------------------------------------
__device__ __forceinline__ void insert16(float d, int id, float bd[KNN], int bi[KNN]) {
#pragma unroll
    for (int t = 0; t < KNN; ++t) {
        bool p = d < bd[t];
        float td = bd[t]; int ti = bi[t];
        bd[t] = p ? d : bd[t];
        bi[t] = p ? id : bi[t];
        d  = p ? td : d;
        id = p ? ti : id;
    }
}

// ---------------------------------------------------------------------------
// Kernel 1: KNN with deferred-batch insertion (windowed uniform flush)
// key = |m|^2 - 2*q.m  (query |q|^2 dropped: constant per query, same order)
// ---------------------------------------------------------------------------
#define KCHUNK 2048
#define WIN    128
#define CAP    16
__global__ void __launch_bounds__(128) knn_kernel(const float* __restrict__ coords) {
    __shared__ float4 s_pt[KCHUNK];
    __shared__ float  s_bd[CAP * 128];
    __shared__ int    s_bi[CAP * 128];

    const int tid = threadIdx.x;
    const int b = blockIdx.y;
    const int q = blockIdx.x * 128 + tid;
    const float* cb = coords + (size_t)b * 3 * NPTS;

    const float qx = cb[q], qy = cb[NPTS + q], qz = cb[2 * NPTS + q];
    const float nx = -2.f * qx, ny = -2.f * qy, nz = -2.f * qz;

    float bd[KNN]; int bi[KNN];
#pragma unroll
    for (int j = 0; j < KNN; ++j) { bd[j] = 3.4e38f; bi[j] = 0; }
    float bd15 = bd[KNN - 1];
    int cnt = 0;

    for (int c0 = 0; c0 < NPTS; c0 += KCHUNK) {
        __syncthreads();
        for (int j = tid; j < KCHUNK; j += 128) {
            float x = cb[c0 + j];
            float y = cb[NPTS + c0 + j];
            float z = cb[2 * NPTS + c0 + j];
            s_pt[j] = make_float4(x, y, z, fmaf(z, z, fmaf(y, y, x * x)));
        }
        __syncthreads();

        if (c0 == 0) {
            // warm-up chunk: hits dense, direct insertion
#pragma unroll 4
            for (int j = 0; j < KCHUNK; ++j) {
                float4 p = s_pt[j];
                float d = fmaf(nx, p.x, fmaf(ny, p.y, fmaf(nz, p.z, p.w)));
                if (d < bd15) { insert16(d, j, bd, bi); bd15 = bd[KNN - 1]; }
            }
        } else {
            for (int w0 = 0; w0 < KCHUNK; w0 += WIN) {
#pragma unroll 4
                for (int j = w0; j < w0 + WIN; ++j) {
                    float4 p = s_pt[j];
                    float d = fmaf(nx, p.x, fmaf(ny, p.y, fmaf(nz, p.z, p.w)));
                    if (d < bd15) {
                        if (cnt < CAP) {
                            s_bd[cnt * 128 + tid] = d;
                            s_bi[cnt * 128 + tid] = c0 + j;
                            cnt++;
                        } else {
                            insert16(d, c0 + j, bd, bi);
                            bd15 = bd[KNN - 1];
                        }
                    }
                }
                // uniform flush point (cheap when all cnt==0)
                for (int u = 0; u < cnt; ++u) {
                    float d = s_bd[u * 128 + tid];
                    int  id = s_bi[u * 128 + tid];
                    if (d < bd15) { insert16(d, id, bd, bi); bd15 = bd[KNN - 1]; }
                }
                cnt = 0;
            }
        }
    }
    int* op = g_idx + ((size_t)b * NPTS + q) * KNN;
#pragma unroll
    for (int j = 0; j < KNN; ++j) op[j] = bi[j];
}

// ---------------------------------------------------------------------------
// Kernel 2: feat3[b,n,o] = sum_c w_lin[o,c] * features[b,c,n]  (n-major out)
// ---------------------------------------------------------------------------
__global__ void __launch_bounds__(128) feat3_kernel(const float* __restrict__ features,
                                                    const float* __restrict__ w_lin) {
    __shared__ float sw[F3 * CIN];
    for (int i = threadIdx.x; i < F3 * CIN; i += 128) sw[i] = w_lin[i];

    const int b = blockIdx.y;
    const int n = blockIdx.x * 128 + threadIdx.x;

    float f[CIN];
    const float* fb = features + (size_t)b * CIN * NPTS + n;
#pragma unroll
    for (int c = 0; c < CIN; ++c) f[c] = fb[(size_t)c * NPTS];
    __syncthreads();

    float* outp = g_feat3 + ((size_t)b * NPTS + n) * F3;
    const float4* sw4 = (const float4*)sw;
#pragma unroll 1
    for (int og = 0; og < F3 / 4; ++og) {
        float a0 = 0.f, a1 = 0.f, a2 = 0.f, a3 = 0.f;
#pragma unroll
        for (int c4 = 0; c4 < CIN / 4; ++c4) {
            float4 w0 = sw4[(og * 4 + 0) * 16 + c4];
            float4 w1 = sw4[(og * 4 + 1) * 16 + c4];
            float4 w2 = sw4[(og * 4 + 2) * 16 + c4];
            float4 w3 = sw4[(og * 4 + 3) * 16 + c4];
            int c = c4 * 4;
            a0 = fmaf(w0.x, f[c], fmaf(w0.y, f[c+1], fmaf(w0.z, f[c+2], fmaf(w0.w, f[c+3], a0))));
            a1 = fmaf(w1.x, f[c], fmaf(w1.y, f[c+1], fmaf(w1.z, f[c+2], fmaf(w1.w, f[c+3], a1))));
            a2 = fmaf(w2.x, f[c], fmaf(w2.y, f[c+1], fmaf(w2.z, f[c+2], fmaf(w2.w, f[c+3], a2))));
            a3 = fmaf(w3.x, f[c], fmaf(w3.y, f[c+1], fmaf(w3.z, f[c+2], fmaf(w3.w, f[c+3], a3))));
        }
        ((float4*)outp)[og] = make_float4(a0, a1, a2, a3);
    }
}

// ---------------------------------------------------------------------------
// packed f32x2 helpers
// ---------------------------------------------------------------------------
__device__ __forceinline__ ull pack2(float f) {
    ull r;
    uint u = __float_as_uint(f);
    asm("mov.b64 %0, {%1, %1};" : "=l"(r) : "r"(u));
    return r;
}
__device__ __forceinline__ void fma2(ull& acc, ull a, ull b) {
    asm("fma.rn.f32x2 %0, %1, %2, %0;" : "+l"(acc) : "l"(a), "l"(b));
}
__device__ __forceinline__ float f2lo(ull v) { return __uint_as_float((uint)v); }
__device__ __forceinline__ float f2hi(ull v) { return __uint_as_float((uint)(v >> 32)); }

// 64x64 @ 64x4 tile: thread computes 4 outputs (o=4og..+3) x 4 k's (packed as 2 pairs).
// wcolT: transposed weights [c][o] base shifted to +4*og ; vrow: staging [c][k] base +4*kg
__device__ __forceinline__ void gemm64(ull acc[8], const float* __restrict__ wcolT,
                                       const float* __restrict__ vrow) {
#pragma unroll
    for (int p = 0; p < 8; ++p) acc[p] = 0ull;
#pragma unroll 16
    for (int c = 0; c < 64; ++c) {
        float4 w = *(const float4*)(wcolT + c * 64);
        double2 vv = *(const double2*)(vrow + c * CS);
        ull v0 = __double_as_longlong(vv.x);
        ull v1 = __double_as_longlong(vv.y);
        ull w0 = pack2(w.x), w1 = pack2(w.y), w2 = pack2(w.z), w3 = pack2(w.w);
        fma2(acc[0], w0, v0); fma2(acc[1], w0, v1);
        fma2(acc[2], w1, v0); fma2(acc[3], w1, v1);
        fma2(acc[4], w2, v0); fma2(acc[5], w2, v1);
        fma2(acc[6], w3, v0); fma2(acc[7], w3, v1);
    }
}

#define TEAM_BAR() asm volatile("bar.sync %0, 64;" :: "r"(barid) : "memory")

// ---------------------------------------------------------------------------
// Kernel 3: fused attention. 256 threads = 4 teams of 64; team = one point.
// Thread (og,kg) owns a 4x4 (o,k) register tile through three 64x64 GEMMs.
// ---------------------------------------------------------------------------
__global__ void __launch_bounds__(256) fused_kernel(
    const float* __restrict__ coords,
    const float* __restrict__ w_theta1,
    const float* __restrict__ w_theta2,
    const float* __restrict__ w_gamma1,
    const float* __restrict__ w_gamma2,
    float* __restrict__ out) {
    extern __shared__ float sm[];
    float* wt2T = sm;               // [c][o]
    float* wg1T = sm + 4096;
    float* wg2T = sm + 8192;
    float* wt1T = sm + 12288;       // [c][o] 3x64

    const int tid = threadIdx.x;
    for (int i = tid; i < 4096; i += 256) {
        int o = i >> 6, c = i & 63;
        wt2T[c * 64 + o] = w_theta2[i];
        wg1T[c * 64 + o] = w_gamma1[i];
        wg2T[c * 64 + o] = w_gamma2[i];
    }
    if (tid < 192) {
        int o = tid / 3, c = tid % 3;
        wt1T[c * 64 + o] = w_theta1[tid];
    }
    __syncthreads();

    const int gq  = tid >> 6;
    const int t64 = tid & 63;
    const int og  = t64 >> 2;
    const int kg  = t64 & 3;
    const int barid = gq + 1;

    float* V0   = sm + 12480 + gq * 4096;   // [64][CS]
    float* V1   = V0 + 1280;
    float* AG   = V0 + 2560;
    float* sphi = V0 + 3840;                // [64]
    float4* srel = (float4*)(V0 + 3904);    // [16]
    int*   sidx = (int*)(V0 + 3968);        // [16]

    for (int P = blockIdx.x * PPT + gq; P < BATCH * NPTS; P += gridDim.x * PPT) {
        const int b = P >> 13;
        const int n = P & (NPTS - 1);

        // ---- phase A: indices, rel coords, phi ----
        if (t64 < KNN) {
            int k = t64;
            int ik = g_idx[(size_t)P * KNN + k];
            sidx[k] = ik;
            const float* cb = coords + (size_t)b * 3 * NPTS;
            srel[k] = make_float4(cb[n] - cb[ik],
                                  cb[NPTS + n] - cb[NPTS + ik],
                                  cb[2 * NPTS + n] - cb[2 * NPTS + ik], 0.f);
        }
        sphi[t64] = g_feat3[(size_t)P * F3 + t64];
        TEAM_BAR();

        // ---- phase B: gather psi/alpha; compute t1 = w_theta1 @ rel ----
        {
            int k = t64 & 15, half = t64 >> 4;
            int ik = sidx[k];
            const float* fb = g_feat3 + (size_t)(b * NPTS + ik) * F3;
#pragma unroll
            for (int c4 = 0; c4 < 4; ++c4) {
                int c0 = half * 16 + c4 * 4;
                float4 ps = *(const float4*)(fb + 64 + c0);
                float4 al = *(const float4*)(fb + 128 + c0);
                V1[(c0 + 0) * CS + k] = sphi[c0 + 0] - ps.x;
                V1[(c0 + 1) * CS + k] = sphi[c0 + 1] - ps.y;
                V1[(c0 + 2) * CS + k] = sphi[c0 + 2] - ps.z;
                V1[(c0 + 3) * CS + k] = sphi[c0 + 3] - ps.w;
                AG[(c0 + 0) * CS + k] = al.x;
                AG[(c0 + 1) * CS + k] = al.y;
                AG[(c0 + 2) * CS + k] = al.z;
                AG[(c0 + 3) * CS + k] = al.w;
            }
        }
        {
            float4 r0 = srel[4 * kg + 0], r1 = srel[4 * kg + 1];
            float4 r2 = srel[4 * kg + 2], r3 = srel[4 * kg + 3];
#pragma unroll
            for (int i = 0; i < 4; ++i) {
                int o = 4 * og + i;
                float w0 = wt1T[o], w1 = wt1T[64 + o], w2 = wt1T[128 + o];
                float4 t;
                t.x = fmaf(w2, r0.z, fmaf(w1, r0.y, w0 * r0.x));
                t.y = fmaf(w2, r1.z, fmaf(w1, r1.y, w0 * r1.x));
                t.z = fmaf(w2, r2.z, fmaf(w1, r2.y, w0 * r2.x));
                t.w = fmaf(w2, r3.z, fmaf(w1, r3.y, w0 * r3.x));
                *(float4*)&V0[o * CS + 4 * kg] = t;
            }
        }
        TEAM_BAR();

        // ---- phase C: delta = relu(w_theta2 @ t1); V1 += delta; AG += delta ----
        ull acc[8];
        gemm64(acc, wt2T + 4 * og, V0 + 4 * kg);
#pragma unroll
        for (int i = 0; i < 4; ++i) {
            float d0 = fmaxf(f2lo(acc[2*i]),   0.f);
            float d1 = fmaxf(f2hi(acc[2*i]),   0.f);
            float d2 = fmaxf(f2lo(acc[2*i+1]), 0.f);
            float d3 = fmaxf(f2hi(acc[2*i+1]), 0.f);
            int o = 4 * og + i;
            float4* pv = (float4*)&V1[o * CS + 4 * kg];
            float4 v = *pv; v.x += d0; v.y += d1; v.z += d2; v.w += d3; *pv = v;
            float4* pa = (float4*)&AG[o * CS + 4 * kg];
            float4 a = *pa; a.x += d0; a.y += d1; a.z += d2; a.w += d3; *pa = a;
        }
        TEAM_BAR();

        // ---- phase D: g1 = w_gamma1 @ ig ----
        gemm64(acc, wg1T + 4 * og, V1 + 4 * kg);
#pragma unroll
        for (int i = 0; i < 4; ++i) {
            int o = 4 * og + i;
            *(float4*)&V0[o * CS + 4 * kg] =
                make_float4(f2lo(acc[2*i]), f2hi(acc[2*i]),
                            f2lo(acc[2*i+1]), f2hi(acc[2*i+1]));
        }
        TEAM_BAR();

        // ---- phase E: g = relu(w_gamma2 @ g1); softmax over k; output ----
        gemm64(acc, wg2T + 4 * og, V0 + 4 * kg);
#pragma unroll
        for (int i = 0; i < 4; ++i) {
            float g0 = fmaxf(f2lo(acc[2*i]),   0.f);
            float g1 = fmaxf(f2hi(acc[2*i]),   0.f);
            float g2 = fmaxf(f2lo(acc[2*i+1]), 0.f);
            float g3 = fmaxf(f2hi(acc[2*i+1]), 0.f);
            float m = fmaxf(fmaxf(g0, g1), fmaxf(g2, g3));
            m = fmaxf(m, __shfl_xor_sync(0xffffffffu, m, 1));
            m = fmaxf(m, __shfl_xor_sync(0xffffffffu, m, 2));
            float e0 = __expf(g0 - m), e1 = __expf(g1 - m);
            float e2 = __expf(g2 - m), e3 = __expf(g3 - m);
            float s = (e0 + e1) + (e2 + e3);
            float4 a = *(const float4*)&AG[(4 * og + i) * CS + 4 * kg];
            float num = fmaf(e0, a.x, fmaf(e1, a.y, fmaf(e2, a.z, e3 * a.w)));
            s   += __shfl_xor_sync(0xffffffffu, s, 1);
            num += __shfl_xor_sync(0xffffffffu, num, 1);
            s   += __shfl_xor_sync(0xffffffffu, s, 2);
            num += __shfl_xor_sync(0xffffffffu, num, 2);
            if (kg == 0)
                out[((size_t)b * CO + 4 * og + i) * NPTS + n] = num / s;
        }
    }
}

// ---------------------------------------------------------------------------
#define FUSED_SMEM ((12480 + PPT * 4096) * sizeof(float))
extern "C" void kernel_launch(void* const* d_in, const int* in_sizes, int n_in,
                              void* d_out, int out_size) {
    const float* features = (const float*)d_in[0];
    const float* coords   = (const float*)d_in[1];
    const float* w_lin    = (const float*)d_in[2];
    const float* w_theta1 = (const float*)d_in[3];
    const float* w_theta2 = (const float*)d_in[4];
    const float* w_gamma1 = (const float*)d_in[5];
    const float* w_gamma2 = (const float*)d_in[6];
    float* out = (float*)d_out;

    static bool attr_set = false;
    if (!attr_set) {
        cudaFuncSetAttribute(fused_kernel, cudaFuncAttributeMaxDynamicSharedMemorySize,
                             FUSED_SMEM);
        attr_set = true;
    }

    knn_kernel<<<dim3(NPTS / 128, BATCH), 128>>>(coords);
    feat3_kernel<<<dim3(NPTS / 128, BATCH), 128>>>(features, w_lin);
    fused_kernel<<<2048, 256, FUSED_SMEM>>>(coords, w_theta1, w_theta2,
                                            w_gamma1, w_gamma2, out);
}

// round 4
// speedup vs baseline: 2.6277x; 1.3781x over previous
#include <cuda_runtime.h>
#include <cstdint>

#define BATCH 4
#define NPTS  8192
#define KNN   16
#define CIN   64
#define CO    64
#define F3    192
#define CS    20
#define PPT   4
#define NQ    (BATCH * NPTS)
#define CHUNKS 4
#define CPC   (NPTS / CHUNKS)    // 2048 candidates per chunk

typedef unsigned long long ull;
typedef unsigned int uint;

__device__ int   g_idx[NQ * KNN];
__device__ float g_feat3[(size_t)NQ * F3];
__device__ float g_pd[CHUNKS * NQ * KNN];
__device__ int   g_pi[CHUNKS * NQ * KNN];
__device__ float g_WgT[CO * CO];   // [c][o] = (w_gamma2 @ w_gamma1)^T
__device__ float g_WtT[3 * CO];    // [c3][o] = (w_theta2 @ w_theta1)^T

// ---------------------------------------------------------------------------
__device__ __forceinline__ void insert16(float d, int id, float bd[KNN], int bi[KNN]) {
#pragma unroll
    for (int t = 0; t < KNN; ++t) {
        bool p = d < bd[t];
        float td = bd[t]; int ti = bi[t];
        bd[t] = p ? d : bd[t];
        bi[t] = p ? id : bi[t];
        d  = p ? td : d;
        id = p ? ti : id;
    }
}

// ---------------------------------------------------------------------------
// Kernel 1: partial KNN over one candidate chunk, geometric-window deferral.
// key = |m|^2 - 2 q.m  (query norm dropped; order-preserving)
// ---------------------------------------------------------------------------
struct KnnState {
    float bd[KNN]; int bi[KNN];
    float bd15; int cnt;
};

__device__ __forceinline__ void scan_flush(const float4* __restrict__ s_pt,
                                           int j0, int j1, int joff,
                                           float nx, float ny, float nz,
                                           KnnState& st, float* s_bd, int* s_bi, int tid) {
#pragma unroll 4
    for (int j = j0; j < j1; ++j) {
        float4 p = s_pt[j];
        float d = fmaf(nx, p.x, fmaf(ny, p.y, fmaf(nz, p.z, p.w)));
        if (d < st.bd15) {
            if (st.cnt < KNN) {
                s_bd[st.cnt * 128 + tid] = d;
                s_bi[st.cnt * 128 + tid] = joff + j;
                st.cnt++;
            } else {
                insert16(d, joff + j, st.bd, st.bi);
                st.bd15 = st.bd[KNN - 1];
            }
        }
    }
    for (int u = 0; u < st.cnt; ++u) {
        float d = s_bd[u * 128 + tid];
        if (d < st.bd15) {
            insert16(d, s_bi[u * 128 + tid], st.bd, st.bi);
            st.bd15 = st.bd[KNN - 1];
        }
    }
    st.cnt = 0;
}

#define SUBT 1024
__global__ void __launch_bounds__(128) knn_part(const float* __restrict__ coords) {
    __shared__ float4 s_pt[SUBT];
    __shared__ float  s_bd[KNN * 128];
    __shared__ int    s_bi[KNN * 128];

    const int tid = threadIdx.x;
    const int b = blockIdx.y;
    const int chunk = blockIdx.z;
    const int q = blockIdx.x * 128 + tid;
    const float* cb = coords + (size_t)b * 3 * NPTS;

    const float qx = cb[q], qy = cb[NPTS + q], qz = cb[2 * NPTS + q];
    const float nx = -2.f * qx, ny = -2.f * qy, nz = -2.f * qz;

    KnnState st;
#pragma unroll
    for (int j = 0; j < KNN; ++j) { st.bd[j] = 3.4e38f; st.bi[j] = 0; }
    st.bd15 = 3.4e38f; st.cnt = 0;

    const int cbase = chunk * CPC;

    for (int sub = 0; sub < CPC / SUBT; ++sub) {
        const int t0 = cbase + sub * SUBT;
        __syncthreads();
        for (int j = tid; j < SUBT; j += 128) {
            float x = cb[t0 + j];
            float y = cb[NPTS + t0 + j];
            float z = cb[2 * NPTS + t0 + j];
            s_pt[j] = make_float4(x, y, z, fmaf(z, z, fmaf(y, y, x * x)));
        }
        __syncthreads();

        if (sub == 0) {
            // direct fill first 16 (everything inserts anyway)
            for (int j = 0; j < KNN; ++j) {
                float4 p = s_pt[j];
                float d = fmaf(nx, p.x, fmaf(ny, p.y, fmaf(nz, p.z, p.w)));
                insert16(d, t0 + j, st.bd, st.bi);
            }
            st.bd15 = st.bd[KNN - 1];
            // geometric windows
            scan_flush(s_pt, 16,  32,   t0, nx, ny, nz, st, s_bd, s_bi, tid);
            scan_flush(s_pt, 32,  64,   t0, nx, ny, nz, st, s_bd, s_bi, tid);
            scan_flush(s_pt, 64,  128,  t0, nx, ny, nz, st, s_bd, s_bi, tid);
            scan_flush(s_pt, 128, 256,  t0, nx, ny, nz, st, s_bd, s_bi, tid);
            scan_flush(s_pt, 256, 512,  t0, nx, ny, nz, st, s_bd, s_bi, tid);
            scan_flush(s_pt, 512, 1024, t0, nx, ny, nz, st, s_bd, s_bi, tid);
        } else {
            scan_flush(s_pt, 0, SUBT, t0, nx, ny, nz, st, s_bd, s_bi, tid);
        }
    }

    const int qg = b * NPTS + q;
    float* pd = g_pd + ((size_t)chunk * NQ + qg) * KNN;
    int*   pi = g_pi + ((size_t)chunk * NQ + qg) * KNN;
#pragma unroll
    for (int j = 0; j < KNN; ++j) { pd[j] = st.bd[j]; pi[j] = st.bi[j]; }
}

// ---------------------------------------------------------------------------
// Kernel 1b: merge 4 sorted partial lists -> final top-16 indices
// ---------------------------------------------------------------------------
__global__ void __launch_bounds__(256) knn_merge() {
    const int qg = blockIdx.x * 256 + threadIdx.x;
    float bd[KNN]; int bi[KNN];

    const float4* p0d = (const float4*)(g_pd + (size_t)qg * KNN);
    const int4*   p0i = (const int4*)(g_pi + (size_t)qg * KNN);
#pragma unroll
    for (int v = 0; v < 4; ++v) {
        float4 d4 = p0d[v]; int4 i4 = p0i[v];
        bd[4*v] = d4.x; bd[4*v+1] = d4.y; bd[4*v+2] = d4.z; bd[4*v+3] = d4.w;
        bi[4*v] = i4.x; bi[4*v+1] = i4.y; bi[4*v+2] = i4.z; bi[4*v+3] = i4.w;
    }
    float bd15 = bd[KNN - 1];

    for (int c = 1; c < CHUNKS; ++c) {
        const float* pd = g_pd + ((size_t)c * NQ + qg) * KNN;
        const int*   pi = g_pi + ((size_t)c * NQ + qg) * KNN;
        for (int j = 0; j < KNN; ++j) {
            float d = pd[j];
            if (d >= bd15) break;        // lists are sorted ascending
            insert16(d, pi[j], bd, bi);
            bd15 = bd[KNN - 1];
        }
    }
    int* op = g_idx + (size_t)qg * KNN;
#pragma unroll
    for (int j = 0; j < KNN; ++j) op[j] = bi[j];
}

// ---------------------------------------------------------------------------
// Kernel W: precombine weights (no ReLU between layer pairs -> linear fold)
// ---------------------------------------------------------------------------
__global__ void __launch_bounds__(256) wprep(const float* __restrict__ w_theta1,
                                             const float* __restrict__ w_theta2,
                                             const float* __restrict__ w_gamma1,
                                             const float* __restrict__ w_gamma2) {
    __shared__ float s1[4096], s2[4096];
    const int t = threadIdx.x;
    for (int i = t; i < 4096; i += 256) { s1[i] = w_gamma1[i]; s2[i] = w_gamma2[i]; }
    __syncthreads();
    for (int i = t; i < 4096; i += 256) {
        int c = i >> 6, o = i & 63;
        float a = 0.f;
#pragma unroll 16
        for (int m = 0; m < 64; ++m) a = fmaf(s2[o * 64 + m], s1[m * 64 + c], a);
        g_WgT[c * 64 + o] = a;
    }
    if (t < 192) {
        int c3 = t / 64, o = t % 64;
        float a = 0.f;
#pragma unroll 16
        for (int m = 0; m < 64; ++m) a = fmaf(w_theta2[o * 64 + m], w_theta1[m * 3 + c3], a);
        g_WtT[c3 * 64 + o] = a;
    }
}

// ---------------------------------------------------------------------------
// Kernel 2: feat3[b,n,o] = sum_c w_lin[o,c] * features[b,c,n]  (n-major out)
// ---------------------------------------------------------------------------
__global__ void __launch_bounds__(128) feat3_kernel(const float* __restrict__ features,
                                                    const float* __restrict__ w_lin) {
    __shared__ float sw[F3 * CIN];
    for (int i = threadIdx.x; i < F3 * CIN; i += 128) sw[i] = w_lin[i];

    const int b = blockIdx.y;
    const int n = blockIdx.x * 128 + threadIdx.x;

    float f[CIN];
    const float* fb = features + (size_t)b * CIN * NPTS + n;
#pragma unroll
    for (int c = 0; c < CIN; ++c) f[c] = fb[(size_t)c * NPTS];
    __syncthreads();

    float* outp = g_feat3 + ((size_t)b * NPTS + n) * F3;
    const float4* sw4 = (const float4*)sw;
#pragma unroll 1
    for (int og = 0; og < F3 / 4; ++og) {
        float a0 = 0.f, a1 = 0.f, a2 = 0.f, a3 = 0.f;
#pragma unroll
        for (int c4 = 0; c4 < CIN / 4; ++c4) {
            float4 w0 = sw4[(og * 4 + 0) * 16 + c4];
            float4 w1 = sw4[(og * 4 + 1) * 16 + c4];
            float4 w2 = sw4[(og * 4 + 2) * 16 + c4];
            float4 w3 = sw4[(og * 4 + 3) * 16 + c4];
            int c = c4 * 4;
            a0 = fmaf(w0.x, f[c], fmaf(w0.y, f[c+1], fmaf(w0.z, f[c+2], fmaf(w0.w, f[c+3], a0))));
            a1 = fmaf(w1.x, f[c], fmaf(w1.y, f[c+1], fmaf(w1.z, f[c+2], fmaf(w1.w, f[c+3], a1))));
            a2 = fmaf(w2.x, f[c], fmaf(w2.y, f[c+1], fmaf(w2.z, f[c+2], fmaf(w2.w, f[c+3], a2))));
            a3 = fmaf(w3.x, f[c], fmaf(w3.y, f[c+1], fmaf(w3.z, f[c+2], fmaf(w3.w, f[c+3], a3))));
        }
        ((float4*)outp)[og] = make_float4(a0, a1, a2, a3);
    }
}

// ---------------------------------------------------------------------------
// packed f32x2 helpers
// ---------------------------------------------------------------------------
__device__ __forceinline__ ull pack2(float f) {
    ull r; uint u = __float_as_uint(f);
    asm("mov.b64 %0, {%1, %1};" : "=l"(r) : "r"(u));
    return r;
}
__device__ __forceinline__ void fma2(ull& acc, ull a, ull b) {
    asm("fma.rn.f32x2 %0, %1, %2, %0;" : "+l"(acc) : "l"(a), "l"(b));
}
__device__ __forceinline__ float f2lo(ull v) { return __uint_as_float((uint)v); }
__device__ __forceinline__ float f2hi(ull v) { return __uint_as_float((uint)(v >> 32)); }

__device__ __forceinline__ void gemm64(ull acc[8], const float* __restrict__ wcolT,
                                       const float* __restrict__ vrow) {
#pragma unroll
    for (int p = 0; p < 8; ++p) acc[p] = 0ull;
#pragma unroll 16
    for (int c = 0; c < 64; ++c) {
        float4 w = *(const float4*)(wcolT + c * 64);
        double2 vv = *(const double2*)(vrow + c * CS);
        ull v0 = __double_as_longlong(vv.x);
        ull v1 = __double_as_longlong(vv.y);
        ull w0 = pack2(w.x), w1 = pack2(w.y), w2 = pack2(w.z), w3 = pack2(w.w);
        fma2(acc[0], w0, v0); fma2(acc[1], w0, v1);
        fma2(acc[2], w1, v0); fma2(acc[3], w1, v1);
        fma2(acc[4], w2, v0); fma2(acc[5], w2, v1);
        fma2(acc[6], w3, v0); fma2(acc[7], w3, v1);
    }
}

#define TEAM_BAR() asm volatile("bar.sync %0, 64;" :: "r"(barid) : "memory")

// ---------------------------------------------------------------------------
// Kernel 3: fused attention, single folded gamma GEMM per (n,k).
// ---------------------------------------------------------------------------
#define TA 2560   // per-team floats: ig[64*CS] + AG[64*CS]
__global__ void __launch_bounds__(256) fused_kernel(const float* __restrict__ coords,
                                                    float* __restrict__ out) {
    extern __shared__ float sm[];
    float* sWgT = sm;            // 4096  [c][o]
    float* sWtT = sm + 4096;     // 192   [c3][o]

    const int tid = threadIdx.x;
    for (int i = tid; i < 4096; i += 256) sWgT[i] = g_WgT[i];
    if (tid < 192) sWtT[tid] = g_WtT[tid];
    __syncthreads();

    const int gq  = tid >> 6;
    const int t64 = tid & 63;
    const int og  = t64 >> 2;
    const int kg  = t64 & 3;
    const int k    = t64 & 15;
    const int half = t64 >> 4;
    const int barid = gq + 1;

    float* ig = sm + 4288 + gq * TA;   // [64][CS]
    float* AG = ig + 1280;             // [64][CS]

    for (int P = blockIdx.x * PPT + gq; P < NQ; P += gridDim.x * PPT) {
        const int b = P >> 13;
        const int n = P & (NPTS - 1);

        // ---- gather + delta + staging ----
        {
            int ik = g_idx[(size_t)P * KNN + k];
            const float* cb = coords + (size_t)b * 3 * NPTS;
            float rx = cb[n]            - cb[ik];
            float ry = cb[NPTS + n]     - cb[NPTS + ik];
            float rz = cb[2 * NPTS + n] - cb[2 * NPTS + ik];

            const float* fb = g_feat3 + (size_t)(b * NPTS + ik) * F3;
            const float* fq = g_feat3 + (size_t)P * F3;
#pragma unroll
            for (int c4 = 0; c4 < 4; ++c4) {
                int c = half * 16 + c4 * 4;
                float4 ph = *(const float4*)(fq + c);
                float4 ps = *(const float4*)(fb + 64 + c);
                float4 al = *(const float4*)(fb + 128 + c);
                float4 w0 = *(const float4*)(sWtT + c);
                float4 w1 = *(const float4*)(sWtT + 64 + c);
                float4 w2 = *(const float4*)(sWtT + 128 + c);
                float d0 = fmaxf(fmaf(w2.x, rz, fmaf(w1.x, ry, w0.x * rx)), 0.f);
                float d1 = fmaxf(fmaf(w2.y, rz, fmaf(w1.y, ry, w0.y * rx)), 0.f);
                float d2 = fmaxf(fmaf(w2.z, rz, fmaf(w1.z, ry, w0.z * rx)), 0.f);
                float d3 = fmaxf(fmaf(w2.w, rz, fmaf(w1.w, ry, w0.w * rx)), 0.f);
                ig[(c + 0) * CS + k] = ph.x - ps.x + d0;
                ig[(c + 1) * CS + k] = ph.y - ps.y + d1;
                ig[(c + 2) * CS + k] = ph.z - ps.z + d2;
                ig[(c + 3) * CS + k] = ph.w - ps.w + d3;
                AG[(c + 0) * CS + k] = al.x + d0;
                AG[(c + 1) * CS + k] = al.y + d1;
                AG[(c + 2) * CS + k] = al.z + d2;
                AG[(c + 3) * CS + k] = al.w + d3;
            }
        }
        TEAM_BAR();

        // ---- g = relu(Wg @ ig); softmax over k; weighted sum ----
        ull acc[8];
        gemm64(acc, sWgT + 4 * og, ig + 4 * kg);
#pragma unroll
        for (int i = 0; i < 4; ++i) {
            float g0 = fmaxf(f2lo(acc[2*i]),   0.f);
            float g1 = fmaxf(f2hi(acc[2*i]),   0.f);
            float g2 = fmaxf(f2lo(acc[2*i+1]), 0.f);
            float g3 = fmaxf(f2hi(acc[2*i+1]), 0.f);
            float m = fmaxf(fmaxf(g0, g1), fmaxf(g2, g3));
            m = fmaxf(m, __shfl_xor_sync(0xffffffffu, m, 1));
            m = fmaxf(m, __shfl_xor_sync(0xffffffffu, m, 2));
            float e0 = __expf(g0 - m), e1 = __expf(g1 - m);
            float e2 = __expf(g2 - m), e3 = __expf(g3 - m);
            float s = (e0 + e1) + (e2 + e3);
            float4 a = *(const float4*)&AG[(4 * og + i) * CS + 4 * kg];
            float num = fmaf(e0, a.x, fmaf(e1, a.y, fmaf(e2, a.z, e3 * a.w)));
            s   += __shfl_xor_sync(0xffffffffu, s, 1);
            num += __shfl_xor_sync(0xffffffffu, num, 1);
            s   += __shfl_xor_sync(0xffffffffu, s, 2);
            num += __shfl_xor_sync(0xffffffffu, num, 2);
            if (kg == 0)
                out[((size_t)b * CO + 4 * og + i) * NPTS + n] = num / s;
        }
        TEAM_BAR();   // protect smem reuse across iterations
    }
}

// ---------------------------------------------------------------------------
#define FUSED_SMEM ((4288 + PPT * TA) * sizeof(float))
extern "C" void kernel_launch(void* const* d_in, const int* in_sizes, int n_in,
                              void* d_out, int out_size) {
    const float* features = (const float*)d_in[0];
    const float* coords   = (const float*)d_in[1];
    const float* w_lin    = (const float*)d_in[2];
    const float* w_theta1 = (const float*)d_in[3];
    const float* w_theta2 = (const float*)d_in[4];
    const float* w_gamma1 = (const float*)d_in[5];
    const float* w_gamma2 = (const float*)d_in[6];
    float* out = (float*)d_out;

    static bool attr_set = false;
    if (!attr_set) {
        cudaFuncSetAttribute(fused_kernel, cudaFuncAttributeMaxDynamicSharedMemorySize,
                             FUSED_SMEM);
        attr_set = true;
    }

    knn_part<<<dim3(NPTS / 128, BATCH, CHUNKS), 128>>>(coords);
    wprep<<<1, 256>>>(w_theta1, w_theta2, w_gamma1, w_gamma2);
    feat3_kernel<<<dim3(NPTS / 128, BATCH), 128>>>(features, w_lin);
    knn_merge<<<NQ / 256, 256>>>();
    fused_kernel<<<2048, 256, FUSED_SMEM>>>(coords, out);
}